// round 9
// baseline (speedup 1.0000x reference)
#include <cuda_runtime.h>
#include <math_constants.h>
#include <cstdint>

#define Ss   384
#define Ee   512
#define Dd   64
#define Hh   8
#define Rr   767
#define RP   768
#define BHn  64
#define MSn  3072
#define SCALE_F 0.07216878364870322f
#define SC2_F   (0.07216878364870322f * 1.44269504088896340736f)   // SCALE * log2(e)

// ---------------- scratch ----------------
static __device__ float g_Q  [MSn * Ee];
static __device__ float g_Km [MSn * Ee];
static __device__ float g_V  [MSn * Ee];
static __device__ float g_ctx[MSn * Ee];
static __device__ float g_Pk [Rr * Ee];
static __device__ float g_Pq [Rr * Ee];
static __device__ float g_Ck [(size_t)BHn * Ss * RP];
static __device__ float g_Cq [(size_t)BHn * Ss * RP];

// ---------------- tf32 mma helpers ----------------
__device__ __forceinline__ uint32_t f2tf32(float x) {
    uint32_t r; asm("cvt.rna.tf32.f32 %0, %1;" : "=r"(r) : "f"(x)); return r;
}
__device__ __forceinline__ void mma8(float* c,
    uint32_t a0, uint32_t a1, uint32_t a2, uint32_t a3, uint32_t b0, uint32_t b1)
{
    asm volatile(
        "mma.sync.aligned.m16n8k8.row.col.f32.tf32.tf32.f32 "
        "{%0,%1,%2,%3}, {%4,%5,%6,%7}, {%8,%9}, {%0,%1,%2,%3};"
        : "+f"(c[0]), "+f"(c[1]), "+f"(c[2]), "+f"(c[3])
        : "r"(a0), "r"(a1), "r"(a2), "r"(a3), "r"(b0), "r"(b1));
}

// FMA-pipe exp2 (no MUFU): degree-5 minimax for 2^f on [0,1), exponent by bit assembly.
__device__ __forceinline__ float exp2f_fast(float y) {
    y = fmaxf(y, -126.0f);
    float fl = floorf(y);
    float f  = y - fl;
    float p = fmaf(f, 0.0018775767f, 0.0089893397f);
    p = fmaf(f, p, 0.0558263180f);
    p = fmaf(f, p, 0.2401536137f);
    p = fmaf(f, p, 0.6931530732f);
    p = fmaf(f, p, 0.9999999702f);
    return __int_as_float(((int)fl + 127) << 23) * p;
}

struct GemmSet { const float* A; const float* W; const float* bias; float* C; int M; };
struct ProjArgs { GemmSet s[5]; };

// =====================================================================
// Core 128x128 tf32 tile:  C = A[M,K] @ W[N,K]^T (+bias)
// =====================================================================
__device__ __forceinline__ void tf32_tile(
    const GemmSet& g, int lda, int ldb, int ldc, int Ncols, int K,
    int m0c, int n0c, uint32_t* As, uint32_t* Bs)
{
    const int tid  = threadIdx.x;
    const int wid  = tid >> 5, lane = tid & 31;
    const int wm   = (wid & 3) * 32, wn = (wid >> 2) * 64;
    const int qr   = lane >> 2, qc = lane & 3;

    float acc[2][8][4];
#pragma unroll
    for (int mf = 0; mf < 2; mf++)
#pragma unroll
        for (int nf = 0; nf < 8; nf++)
#pragma unroll
            for (int c = 0; c < 4; c++) acc[mf][nf][c] = 0.f;

    const int r  = tid >> 1;
    const int kh = (tid & 1) * 16;

    for (int k0 = 0; k0 < K; k0 += 32) {
        const bool arow = (m0c + r) < g.M;
        const bool brow = (n0c + r) < Ncols;
        const float* Ap = g.A + (size_t)(m0c + r) * lda + k0 + kh;
        const float* Bp = g.W + (size_t)(n0c + r) * ldb + k0 + kh;
#pragma unroll
        for (int i = 0; i < 4; i++) {
            float4 va = arow ? *(const float4*)(Ap + 4 * i) : make_float4(0.f, 0.f, 0.f, 0.f);
            uint4 ua; ua.x = f2tf32(va.x); ua.y = f2tf32(va.y);
                      ua.z = f2tf32(va.z); ua.w = f2tf32(va.w);
            *(uint4*)&As[r * 36 + kh + 4 * i] = ua;

            float4 vb = brow ? *(const float4*)(Bp + 4 * i) : make_float4(0.f, 0.f, 0.f, 0.f);
            uint4 ub; ub.x = f2tf32(vb.x); ub.y = f2tf32(vb.y);
                      ub.z = f2tf32(vb.z); ub.w = f2tf32(vb.w);
            *(uint4*)&Bs[r * 36 + kh + 4 * i] = ub;
        }
        __syncthreads();

#pragma unroll
        for (int kk = 0; kk < 4; kk++) {
            const int kb = kk * 8;
            uint32_t a[2][4];
#pragma unroll
            for (int mf = 0; mf < 2; mf++) {
                const int mrow = wm + mf * 16 + qr;
                a[mf][0] = As[(mrow)     * 36 + kb + qc];
                a[mf][1] = As[(mrow + 8) * 36 + kb + qc];
                a[mf][2] = As[(mrow)     * 36 + kb + qc + 4];
                a[mf][3] = As[(mrow + 8) * 36 + kb + qc + 4];
            }
#pragma unroll
            for (int nf = 0; nf < 8; nf++) {
                const int nrow = wn + nf * 8 + qr;
                const uint32_t b0 = Bs[nrow * 36 + kb + qc];
                const uint32_t b1 = Bs[nrow * 36 + kb + qc + 4];
                mma8(acc[0][nf], a[0][0], a[0][1], a[0][2], a[0][3], b0, b1);
                mma8(acc[1][nf], a[1][0], a[1][1], a[1][2], a[1][3], b0, b1);
            }
        }
        __syncthreads();
    }

#pragma unroll
    for (int mf = 0; mf < 2; mf++) {
#pragma unroll
        for (int half = 0; half < 2; half++) {
            const int row = m0c + wm + mf * 16 + qr + half * 8;
            if (row >= g.M) continue;
#pragma unroll
            for (int nf = 0; nf < 8; nf++) {
                const int col = n0c + wn + nf * 8 + 2 * qc;
                float v0 = acc[mf][nf][half * 2 + 0];
                float v1 = acc[mf][nf][half * 2 + 1];
                if (g.bias) { v0 += __ldg(&g.bias[col]); v1 += __ldg(&g.bias[col + 1]); }
                if (col + 1 < Ncols)
                    *(float2*)&g.C[(size_t)row * ldc + col] = make_float2(v0, v1);
                else if (col < Ncols)
                    g.C[(size_t)row * ldc + col] = v0;
            }
        }
    }
}

__global__ __launch_bounds__(256, 2) void tf32_proj(ProjArgs pa)
{
    __shared__ uint32_t As[128 * 36], Bs[128 * 36];
    GemmSet g = pa.s[blockIdx.z];
    const int m0c = blockIdx.y * 128;
    if (m0c >= g.M) return;
    tf32_tile(g, 512, 512, 512, 512, 512, m0c, blockIdx.x * 128, As, Bs);
}

// Per-head bias GEMMs, windowed to the reachable rr band.
__global__ __launch_bounds__(256, 2) void tf32_head(
    const float* __restrict__ Q, const float* __restrict__ Km,
    const float* __restrict__ Pk, const float* __restrict__ Pq,
    float* __restrict__ Ck, float* __restrict__ Cq)
{
    __shared__ uint32_t As[128 * 36], Bs[128 * 36];
    const int z = blockIdx.z, bh = z >> 1, which = z & 1;
    const int b = bh >> 3, h = bh & 7;
    const int m0c = blockIdx.y * 128;
    const int n0c = (which ? m0c : 256 - m0c) + blockIdx.x * 128;
    GemmSet g;
    g.A    = (which ? Km : Q) + (size_t)b * Ss * Ee + h * Dd;
    g.W    = (which ? Pq : Pk) + h * Dd;
    g.bias = nullptr;
    g.C    = (which ? Cq : Ck) + (size_t)bh * Ss * RP;
    g.M    = Ss;
    tf32_tile(g, Ee, Ee, RP, Rr, Dd, m0c, n0c, As, Bs);
}

// =====================================================================
// Flash attention, tf32 mma for QK^T and PV, FMA-pipe softmax,
// Cq diagonal window staged through smem (no sector waste).
// 64 query rows / CTA, 256 threads (8 warps: 2m x 4n), 3 j-tiles of 128.
// =====================================================================
#define LDQ 68
#define LDV 133
#define LDP 132
#define LDCQ 66
#define ATTN_SMEM ((64*68 + 128*68 + 64*132 + 64*3 + 128) * 4)

__global__ __launch_bounds__(256, 2) void attn_mma(
    const float* __restrict__ Q, const float* __restrict__ Km,
    const float* __restrict__ V, const float* __restrict__ Ck,
    const float* __restrict__ Cq, const int* __restrict__ mask,
    float* __restrict__ ctx)
{
    extern __shared__ char smraw[];
    uint32_t* Qs = (uint32_t*)smraw;            // 64 x 68 tf32
    uint32_t* KV = Qs + 64 * LDQ;               // K: 128x68 | Cq window: 128x66 f32 | V^T: 64x133
    float*    KVf = (float*)KV;
    float*    Ps = (float*)(KV + 128 * LDQ);    // 64 x 132 logits/probs
    uint32_t* PsU = (uint32_t*)Ps;
    float* mrow = Ps + 64 * LDP;
    float* lrow = mrow + 64;
    float* crow = lrow + 64;
    int*   msk  = (int*)(crow + 64);

    const int bh = blockIdx.y, b = bh >> 3, h = bh & 7;
    const int i0 = blockIdx.x * 64;
    const int tid = threadIdx.x, wid = tid >> 5, lane = tid & 31;
    const int qr = lane >> 2, qc = lane & 3;
    const int wm  = (wid & 1) * 32;
    const int wn  = (wid >> 1) * 32;
    const int wn2 = (wid >> 1) * 16;

    // Q tile -> tf32 smem
    {
        const int r = tid >> 2, kh = (tid & 3) * 16;
        const float* p = Q + ((size_t)(b * Ss + i0 + r)) * Ee + h * Dd + kh;
#pragma unroll
        for (int i = 0; i < 4; i++) {
            float4 v = *(const float4*)(p + 4 * i);
            uint4 u; u.x = f2tf32(v.x); u.y = f2tf32(v.y);
                     u.z = f2tf32(v.z); u.w = f2tf32(v.w);
            *(uint4*)&Qs[r * LDQ + kh + 4 * i] = u;
        }
    }
    if (tid < 64) { mrow[tid] = -CUDART_INF_F; lrow[tid] = 0.f; }

    float accO[2][2][4];
#pragma unroll
    for (int mf = 0; mf < 2; mf++)
#pragma unroll
        for (int nf = 0; nf < 2; nf++)
#pragma unroll
            for (int c = 0; c < 4; c++) accO[mf][nf][c] = 0.f;

    const size_t cB = (size_t)bh * Ss;

    for (int jt = 0; jt < 3; jt++) {
        const int j0 = jt * 128;
        __syncthreads();   // prev PV reads of KV/Ps done; first iter: Qs/mrow init

        // K tile 128x64 -> tf32
        {
            const int r = tid >> 1, kh = (tid & 1) * 32;
            const float* p = Km + ((size_t)(b * Ss + j0 + r)) * Ee + h * Dd + kh;
#pragma unroll
            for (int i = 0; i < 8; i++) {
                float4 v = *(const float4*)(p + 4 * i);
                uint4 u; u.x = f2tf32(v.x); u.y = f2tf32(v.y);
                         u.z = f2tf32(v.z); u.w = f2tf32(v.w);
                *(uint4*)&KV[r * LDQ + kh + 4 * i] = u;
            }
        }
        if (tid < 128) msk[tid] = mask[b * Ss + j0 + tid];
        __syncthreads();

        // ---- S = Q K^T : M=64, N=128, K=64 ----
        float accS[2][4][4];
#pragma unroll
        for (int mf = 0; mf < 2; mf++)
#pragma unroll
            for (int nf = 0; nf < 4; nf++)
#pragma unroll
                for (int c = 0; c < 4; c++) accS[mf][nf][c] = 0.f;

#pragma unroll
        for (int kk = 0; kk < 8; kk++) {
            const int kb = kk * 8;
            uint32_t a[2][4];
#pragma unroll
            for (int mf = 0; mf < 2; mf++) {
                const int mr = wm + mf * 16 + qr;
                a[mf][0] = Qs[mr * LDQ + kb + qc];
                a[mf][1] = Qs[(mr + 8) * LDQ + kb + qc];
                a[mf][2] = Qs[mr * LDQ + kb + qc + 4];
                a[mf][3] = Qs[(mr + 8) * LDQ + kb + qc + 4];
            }
#pragma unroll
            for (int nf = 0; nf < 4; nf++) {
                const int nr = wn + nf * 8 + qr;
                const uint32_t b0 = KV[nr * LDQ + kb + qc];
                const uint32_t b1 = KV[nr * LDQ + kb + qc + 4];
                mma8(accS[0][nf], a[0][0], a[0][1], a[0][2], a[0][3], b0, b1);
                mma8(accS[1][nf], a[1][0], a[1][1], a[1][2], a[1][3], b0, b1);
            }
        }
        __syncthreads();   // all K reads done; KV free for Cq window

        // ---- Cq diagonal window -> smem: smCq[jl][k] = Cq[jg][jg - i0 + 320 + k] ----
        {
            const int jl = tid >> 1;
            const int c0 = (tid & 1) * 32;
            const int jg = j0 + jl;
            const float* src = Cq + (cB + jg) * RP + (jg - i0 + 320) + c0;
            float* dst = KVf + jl * LDCQ + c0;
#pragma unroll
            for (int u = 0; u < 32; u++) dst[u] = __ldg(src + u);
        }
        __syncthreads();

        // ---- biases + scale(SC2) + mask -> Ps (base-2 logits) ----
#pragma unroll
        for (int mf = 0; mf < 2; mf++) {
#pragma unroll
            for (int half = 0; half < 2; half++) {
                const int rl = wm + mf * 16 + qr + half * 8;
                const int ig = i0 + rl;
                const float* ckRow = Ck + (cB + ig) * RP + (j0 - ig + 383);
                const int kq = 63 - rl;
#pragma unroll
                for (int nf = 0; nf < 4; nf++) {
                    const int col = wn + nf * 8 + 2 * qc;
                    float v0 = (accS[mf][nf][half * 2 + 0]
                              + __ldg(ckRow + col)     + KVf[col * LDCQ + kq]) * SC2_F;
                    float v1 = (accS[mf][nf][half * 2 + 1]
                              + __ldg(ckRow + col + 1) + KVf[(col + 1) * LDCQ + kq]) * SC2_F;
                    if (msk[col] == 0)     v0 = -9.0e15f;
                    if (msk[col + 1] == 0) v1 = -9.0e15f;
                    *(float2*)&Ps[rl * LDP + col] = make_float2(v0, v1);
                }
            }
        }
        __syncthreads();   // Ps complete; Cq reads done -> KV free for V^T

        // ---- V tile -> V^T tf32 (aliases KV) ----
        {
            const int d4 = (tid & 15) * 4, jb = tid >> 4;
            const float* vb = V + ((size_t)(b * Ss + j0)) * Ee + h * Dd + d4;
#pragma unroll
            for (int p2 = 0; p2 < 8; p2++) {
                const int jj = jb + p2 * 16;
                float4 v = *(const float4*)(vb + (size_t)jj * Ee);
                KV[(d4 + 0) * LDV + jj] = f2tf32(v.x);
                KV[(d4 + 1) * LDV + jj] = f2tf32(v.y);
                KV[(d4 + 2) * LDV + jj] = f2tf32(v.z);
                KV[(d4 + 3) * LDV + jj] = f2tf32(v.w);
            }
        }

        // ---- online softmax (base 2, FMA-pipe exp): 4 threads/row ----
        {
            const int row = tid >> 2, q = tid & 3;
            float* pr = Ps + row * LDP;
            const float mo = mrow[row];
            float mx = mo;
#pragma unroll 8
            for (int t = 0; t < 32; t++) mx = fmaxf(mx, pr[q + 4 * t]);
            mx = fmaxf(mx, __shfl_xor_sync(0xffffffffu, mx, 1));
            mx = fmaxf(mx, __shfl_xor_sync(0xffffffffu, mx, 2));
            float sum = 0.f;
#pragma unroll 8
            for (int t = 0; t < 32; t++) {
                const int c = q + 4 * t;
                const float p = exp2f_fast(pr[c] - mx);
                sum += p;
                ((uint32_t*)pr)[c] = f2tf32(p);
            }
            sum += __shfl_xor_sync(0xffffffffu, sum, 1);
            sum += __shfl_xor_sync(0xffffffffu, sum, 2);
            if (q == 0) {
                crow[row] = exp2f_fast(mo - mx);
                mrow[row] = mx;
                lrow[row] = lrow[row] * crow[row] + sum;
            }
        }
        __syncthreads();

        // ---- O = O*cf + P @ V : M=64, N=64, K=128 ----
        {
            float cf0[2], cf1[2];
#pragma unroll
            for (int mf = 0; mf < 2; mf++) {
                cf0[mf] = crow[wm + mf * 16 + qr];
                cf1[mf] = crow[wm + mf * 16 + qr + 8];
            }
#pragma unroll
            for (int mf = 0; mf < 2; mf++)
#pragma unroll
                for (int nf = 0; nf < 2; nf++) {
                    accO[mf][nf][0] *= cf0[mf]; accO[mf][nf][1] *= cf0[mf];
                    accO[mf][nf][2] *= cf1[mf]; accO[mf][nf][3] *= cf1[mf];
                }
#pragma unroll
            for (int kk = 0; kk < 16; kk++) {
                const int kb = kk * 8;
                uint32_t a[2][4];
#pragma unroll
                for (int mf = 0; mf < 2; mf++) {
                    const int mr = wm + mf * 16 + qr;
                    a[mf][0] = PsU[mr * LDP + kb + qc];
                    a[mf][1] = PsU[(mr + 8) * LDP + kb + qc];
                    a[mf][2] = PsU[mr * LDP + kb + qc + 4];
                    a[mf][3] = PsU[(mr + 8) * LDP + kb + qc + 4];
                }
#pragma unroll
                for (int nf = 0; nf < 2; nf++) {
                    const int nr = wn2 + nf * 8 + qr;
                    const uint32_t b0 = KV[nr * LDV + kb + qc];
                    const uint32_t b1 = KV[nr * LDV + kb + qc + 4];
                    mma8(accO[0][nf], a[0][0], a[0][1], a[0][2], a[0][3], b0, b1);
                    mma8(accO[1][nf], a[1][0], a[1][1], a[1][2], a[1][3], b0, b1);
                }
            }
        }
    }

    // ---- finalize ----
#pragma unroll
    for (int mf = 0; mf < 2; mf++) {
#pragma unroll
        for (int half = 0; half < 2; half++) {
            const int rl = wm + mf * 16 + qr + half * 8;
            const float inv = 1.f / lrow[rl];
#pragma unroll
            for (int nf = 0; nf < 2; nf++) {
                const int col = wn2 + nf * 8 + 2 * qc;
                float2 o;
                o.x = accO[mf][nf][half * 2 + 0] * inv;
                o.y = accO[mf][nf][half * 2 + 1] * inv;
                *(float2*)&ctx[((size_t)(b * Ss + i0 + rl)) * Ee + h * Dd + col] = o;
            }
        }
    }
}

// =====================================================================
// Host launcher
// =====================================================================
extern "C" void kernel_launch(void* const* d_in, const int* in_sizes, int n_in,
                              void* d_out, int out_size)
{
    const float* x    = (const float*)d_in[0];
    const int*   mask = (const int*)  d_in[1];
    const float* Wq   = (const float*)d_in[2];
    const float* bq   = (const float*)d_in[3];
    const float* Wk   = (const float*)d_in[4];
    const float* bk   = (const float*)d_in[5];
    const float* Wv   = (const float*)d_in[6];
    const float* bv   = (const float*)d_in[7];
    const float* rel  = (const float*)d_in[8];
    const float* Wpk  = (const float*)d_in[9];
    const float* bpk  = (const float*)d_in[10];
    const float* Wpq  = (const float*)d_in[11];
    const float* bpq  = (const float*)d_in[12];
    const float* Wo   = (const float*)d_in[13];
    const float* bo   = (const float*)d_in[14];
    float* out = (float*)d_out;

    float *Q, *Km, *V, *ctx, *Pk, *Pq, *Ck, *Cq;
    cudaGetSymbolAddress((void**)&Q,   g_Q);
    cudaGetSymbolAddress((void**)&Km,  g_Km);
    cudaGetSymbolAddress((void**)&V,   g_V);
    cudaGetSymbolAddress((void**)&ctx, g_ctx);
    cudaGetSymbolAddress((void**)&Pk,  g_Pk);
    cudaGetSymbolAddress((void**)&Pq,  g_Pq);
    cudaGetSymbolAddress((void**)&Ck,  g_Ck);
    cudaGetSymbolAddress((void**)&Cq,  g_Cq);

    cudaFuncSetAttribute(attn_mma,
                         cudaFuncAttributeMaxDynamicSharedMemorySize, ATTN_SMEM);

    const float* relS = rel + 128 * 512;

    ProjArgs pa;
    pa.s[0] = { x,    Wq,  bq,  Q,   MSn };
    pa.s[1] = { x,    Wk,  bk,  Km,  MSn };
    pa.s[2] = { x,    Wv,  bv,  V,   MSn };
    pa.s[3] = { relS, Wpk, bpk, Pk,  Rr  };
    pa.s[4] = { relS, Wpq, bpq, Pq,  Rr  };
    tf32_proj<<<dim3(4, 24, 5), 256>>>(pa);

    tf32_head<<<dim3(4, 3, 2 * BHn), 256>>>(Q, Km, Pk, Pq, Ck, Cq);

    attn_mma<<<dim3(6, BHn), 256, ATTN_SMEM>>>(Q, Km, V, Ck, Cq, mask, ctx);

    ProjArgs po;
    po.s[0] = { ctx, Wo, bo, out, MSn };
    po.s[1] = po.s[0]; po.s[2] = po.s[0]; po.s[3] = po.s[0]; po.s[4] = po.s[0];
    tf32_proj<<<dim3(4, 24, 1), 256>>>(po);
}

// round 10
// speedup vs baseline: 1.5851x; 1.5851x over previous
#include <cuda_runtime.h>
#include <math_constants.h>
#include <cstdint>

#define Ss   384
#define Ee   512
#define Dd   64
#define Hh   8
#define Rr   767
#define RP   768
#define BHn  64
#define MSn  3072
#define SCALE_F 0.07216878364870322f

// ---------------- scratch ----------------
static __device__ float g_Q  [MSn * Ee];
static __device__ float g_Km [MSn * Ee];
static __device__ float g_V  [MSn * Ee];
static __device__ float g_ctx[MSn * Ee];
static __device__ float g_Pk [Rr * Ee];
static __device__ float g_Pq [Rr * Ee];
static __device__ float g_Ck [(size_t)BHn * Ss * RP];
static __device__ float g_Cq [(size_t)BHn * Ss * RP];

// ---------------- tf32 mma helpers ----------------
__device__ __forceinline__ uint32_t f2tf32(float x) {
    uint32_t r; asm("cvt.rna.tf32.f32 %0, %1;" : "=r"(r) : "f"(x)); return r;
}
__device__ __forceinline__ void mma8(float* c,
    uint32_t a0, uint32_t a1, uint32_t a2, uint32_t a3, uint32_t b0, uint32_t b1)
{
    asm volatile(
        "mma.sync.aligned.m16n8k8.row.col.f32.tf32.tf32.f32 "
        "{%0,%1,%2,%3}, {%4,%5,%6,%7}, {%8,%9}, {%0,%1,%2,%3};"
        : "+f"(c[0]), "+f"(c[1]), "+f"(c[2]), "+f"(c[3])
        : "r"(a0), "r"(a1), "r"(a2), "r"(a3), "r"(b0), "r"(b1));
}

struct GemmSet { const float* A; const float* W; const float* bias; float* C; int M; };
struct ProjArgs { GemmSet s[5]; };

// =====================================================================
// 64x128 tf32 tile (projections): C = A[M,512] @ W[512,512]^T + bias
// 256 threads = 8 warps (2m x 4n), warp tile 32x32, BK=32.
// Half the per-CTA work of the 128-tile -> 2 CTAs/SM, 2x latency hiding.
// =====================================================================
__global__ __launch_bounds__(256) void tf32_proj(ProjArgs pa)
{
    __shared__ uint32_t As[64 * 36];
    __shared__ uint32_t Bs[128 * 36];

    GemmSet g = pa.s[blockIdx.z];
    const int m0c = blockIdx.y * 64;
    if (m0c >= g.M) return;
    const int n0c = blockIdx.x * 128;

    const int tid  = threadIdx.x;
    const int wid  = tid >> 5, lane = tid & 31;
    const int wm   = (wid & 1) * 32, wn = (wid >> 1) * 32;
    const int qr   = lane >> 2, qc = lane & 3;

    float acc[2][4][4];
#pragma unroll
    for (int mf = 0; mf < 2; mf++)
#pragma unroll
        for (int nf = 0; nf < 4; nf++)
#pragma unroll
            for (int c = 0; c < 4; c++) acc[mf][nf][c] = 0.f;

    const int rb  = tid >> 1;            // B row 0..127
    const int kb8 = (tid & 1) * 16;
    const int ra  = tid >> 2;            // A row 0..63
    const int ka8 = (tid & 3) * 8;

    for (int k0 = 0; k0 < 512; k0 += 32) {
        // A: 64 rows x 32 k
        {
            const bool ok = (m0c + ra) < g.M;
            const float* Ap = g.A + (size_t)(m0c + ra) * 512 + k0 + ka8;
#pragma unroll
            for (int i = 0; i < 2; i++) {
                float4 v = ok ? *(const float4*)(Ap + 4 * i) : make_float4(0.f, 0.f, 0.f, 0.f);
                uint4 u; u.x = f2tf32(v.x); u.y = f2tf32(v.y);
                         u.z = f2tf32(v.z); u.w = f2tf32(v.w);
                *(uint4*)&As[ra * 36 + ka8 + 4 * i] = u;
            }
        }
        // B: 128 rows x 32 k
        {
            const float* Bp = g.W + (size_t)(n0c + rb) * 512 + k0 + kb8;
#pragma unroll
            for (int i = 0; i < 4; i++) {
                float4 v = *(const float4*)(Bp + 4 * i);
                uint4 u; u.x = f2tf32(v.x); u.y = f2tf32(v.y);
                         u.z = f2tf32(v.z); u.w = f2tf32(v.w);
                *(uint4*)&Bs[rb * 36 + kb8 + 4 * i] = u;
            }
        }
        __syncthreads();

#pragma unroll
        for (int kk = 0; kk < 4; kk++) {
            const int kbase = kk * 8;
            uint32_t a[2][4];
#pragma unroll
            for (int mf = 0; mf < 2; mf++) {
                const int mr = wm + mf * 16 + qr;
                a[mf][0] = As[(mr)     * 36 + kbase + qc];
                a[mf][1] = As[(mr + 8) * 36 + kbase + qc];
                a[mf][2] = As[(mr)     * 36 + kbase + qc + 4];
                a[mf][3] = As[(mr + 8) * 36 + kbase + qc + 4];
            }
#pragma unroll
            for (int nf = 0; nf < 4; nf++) {
                const int nr = wn + nf * 8 + qr;
                const uint32_t b0 = Bs[nr * 36 + kbase + qc];
                const uint32_t b1 = Bs[nr * 36 + kbase + qc + 4];
                mma8(acc[0][nf], a[0][0], a[0][1], a[0][2], a[0][3], b0, b1);
                mma8(acc[1][nf], a[1][0], a[1][1], a[1][2], a[1][3], b0, b1);
            }
        }
        __syncthreads();
    }

#pragma unroll
    for (int mf = 0; mf < 2; mf++) {
#pragma unroll
        for (int half = 0; half < 2; half++) {
            const int row = m0c + wm + mf * 16 + qr + half * 8;
            if (row >= g.M) continue;
#pragma unroll
            for (int nf = 0; nf < 4; nf++) {
                const int col = n0c + wn + nf * 8 + 2 * qc;
                float v0 = acc[mf][nf][half * 2 + 0] + __ldg(&g.bias[col]);
                float v1 = acc[mf][nf][half * 2 + 1] + __ldg(&g.bias[col + 1]);
                *(float2*)&g.C[(size_t)row * 512 + col] = make_float2(v0, v1);
            }
        }
    }
}

// =====================================================================
// 128x128 tf32 tile (head GEMMs): C = A[M,K] @ W[N,K]^T  (K=64)
// =====================================================================
__device__ __forceinline__ void tf32_tile(
    const GemmSet& g, int lda, int ldb, int ldc, int Ncols, int K,
    int m0c, int n0c, uint32_t* As, uint32_t* Bs)
{
    const int tid  = threadIdx.x;
    const int wid  = tid >> 5, lane = tid & 31;
    const int wm   = (wid & 3) * 32, wn = (wid >> 2) * 64;
    const int qr   = lane >> 2, qc = lane & 3;

    float acc[2][8][4];
#pragma unroll
    for (int mf = 0; mf < 2; mf++)
#pragma unroll
        for (int nf = 0; nf < 8; nf++)
#pragma unroll
            for (int c = 0; c < 4; c++) acc[mf][nf][c] = 0.f;

    const int r  = tid >> 1;
    const int kh = (tid & 1) * 16;

    for (int k0 = 0; k0 < K; k0 += 32) {
        const bool arow = (m0c + r) < g.M;
        const bool brow = (n0c + r) < Ncols;
        const float* Ap = g.A + (size_t)(m0c + r) * lda + k0 + kh;
        const float* Bp = g.W + (size_t)(n0c + r) * ldb + k0 + kh;
#pragma unroll
        for (int i = 0; i < 4; i++) {
            float4 va = arow ? *(const float4*)(Ap + 4 * i) : make_float4(0.f, 0.f, 0.f, 0.f);
            uint4 ua; ua.x = f2tf32(va.x); ua.y = f2tf32(va.y);
                      ua.z = f2tf32(va.z); ua.w = f2tf32(va.w);
            *(uint4*)&As[r * 36 + kh + 4 * i] = ua;

            float4 vb = brow ? *(const float4*)(Bp + 4 * i) : make_float4(0.f, 0.f, 0.f, 0.f);
            uint4 ub; ub.x = f2tf32(vb.x); ub.y = f2tf32(vb.y);
                      ub.z = f2tf32(vb.z); ub.w = f2tf32(vb.w);
            *(uint4*)&Bs[r * 36 + kh + 4 * i] = ub;
        }
        __syncthreads();

#pragma unroll
        for (int kk = 0; kk < 4; kk++) {
            const int kb = kk * 8;
            uint32_t a[2][4];
#pragma unroll
            for (int mf = 0; mf < 2; mf++) {
                const int mrow = wm + mf * 16 + qr;
                a[mf][0] = As[(mrow)     * 36 + kb + qc];
                a[mf][1] = As[(mrow + 8) * 36 + kb + qc];
                a[mf][2] = As[(mrow)     * 36 + kb + qc + 4];
                a[mf][3] = As[(mrow + 8) * 36 + kb + qc + 4];
            }
#pragma unroll
            for (int nf = 0; nf < 8; nf++) {
                const int nrow = wn + nf * 8 + qr;
                const uint32_t b0 = Bs[nrow * 36 + kb + qc];
                const uint32_t b1 = Bs[nrow * 36 + kb + qc + 4];
                mma8(acc[0][nf], a[0][0], a[0][1], a[0][2], a[0][3], b0, b1);
                mma8(acc[1][nf], a[1][0], a[1][1], a[1][2], a[1][3], b0, b1);
            }
        }
        __syncthreads();
    }

#pragma unroll
    for (int mf = 0; mf < 2; mf++) {
#pragma unroll
        for (int half = 0; half < 2; half++) {
            const int row = m0c + wm + mf * 16 + qr + half * 8;
            if (row >= g.M) continue;
#pragma unroll
            for (int nf = 0; nf < 8; nf++) {
                const int col = n0c + wn + nf * 8 + 2 * qc;
                float v0 = acc[mf][nf][half * 2 + 0];
                float v1 = acc[mf][nf][half * 2 + 1];
                if (col + 1 < Ncols)
                    *(float2*)&g.C[(size_t)row * ldc + col] = make_float2(v0, v1);
                else if (col < Ncols)
                    g.C[(size_t)row * ldc + col] = v0;
            }
        }
    }
}

// Per-head bias GEMMs, windowed to the reachable rr band.
__global__ __launch_bounds__(256) void tf32_head(
    const float* __restrict__ Q, const float* __restrict__ Km,
    const float* __restrict__ Pk, const float* __restrict__ Pq,
    float* __restrict__ Ck, float* __restrict__ Cq)
{
    __shared__ uint32_t As[128 * 36], Bs[128 * 36];
    const int z = blockIdx.z, bh = z >> 1, which = z & 1;
    const int b = bh >> 3, h = bh & 7;
    const int m0c = blockIdx.y * 128;
    const int n0c = (which ? m0c : 256 - m0c) + blockIdx.x * 128;
    GemmSet g;
    g.A    = (which ? Km : Q) + (size_t)b * Ss * Ee + h * Dd;
    g.W    = (which ? Pq : Pk) + h * Dd;
    g.bias = nullptr;
    g.C    = (which ? Cq : Ck) + (size_t)bh * Ss * RP;
    g.M    = Ss;
    tf32_tile(g, Ee, Ee, RP, Rr, Dd, m0c, n0c, As, Bs);
}

// =====================================================================
// Flash attention (R4 version: tf32 mma QK^T / PV, MUFU __expf softmax).
// 64 query rows / CTA, 256 threads (8 warps: 2m x 4n), 3 j-tiles of 128.
// =====================================================================
#define LDQ 68
#define LDV 133
#define LDP 132
#define ATTN_SMEM ((64*68 + 128*68 + 64*132 + 64*3 + 128) * 4)

__global__ __launch_bounds__(256, 2) void attn_mma(
    const float* __restrict__ Q, const float* __restrict__ Km,
    const float* __restrict__ V, const float* __restrict__ Ck,
    const float* __restrict__ Cq, const int* __restrict__ mask,
    float* __restrict__ ctx)
{
    extern __shared__ char smraw[];
    uint32_t* Qs = (uint32_t*)smraw;            // 64 x 68 tf32
    uint32_t* KV = Qs + 64 * LDQ;               // K: 128x68 ; V^T aliased: 64x133
    float*    Ps = (float*)(KV + 128 * LDQ);    // 64 x 132 logits/probs
    uint32_t* PsU = (uint32_t*)Ps;
    float* mrow = Ps + 64 * LDP;
    float* lrow = mrow + 64;
    float* crow = lrow + 64;
    int*   msk  = (int*)(crow + 64);

    const int bh = blockIdx.y, b = bh >> 3, h = bh & 7;
    const int i0 = blockIdx.x * 64;
    const int tid = threadIdx.x, wid = tid >> 5, lane = tid & 31;
    const int qr = lane >> 2, qc = lane & 3;
    const int wm  = (wid & 1) * 32;
    const int wn  = (wid >> 1) * 32;
    const int wn2 = (wid >> 1) * 16;

    // Q tile -> tf32 smem
    {
        const int r = tid >> 2, kh = (tid & 3) * 16;
        const float* p = Q + ((size_t)(b * Ss + i0 + r)) * Ee + h * Dd + kh;
#pragma unroll
        for (int i = 0; i < 4; i++) {
            float4 v = *(const float4*)(p + 4 * i);
            uint4 u; u.x = f2tf32(v.x); u.y = f2tf32(v.y);
                     u.z = f2tf32(v.z); u.w = f2tf32(v.w);
            *(uint4*)&Qs[r * LDQ + kh + 4 * i] = u;
        }
    }
    if (tid < 64) { mrow[tid] = -CUDART_INF_F; lrow[tid] = 0.f; }

    float accO[2][2][4];
#pragma unroll
    for (int mf = 0; mf < 2; mf++)
#pragma unroll
        for (int nf = 0; nf < 2; nf++)
#pragma unroll
            for (int c = 0; c < 4; c++) accO[mf][nf][c] = 0.f;

    const size_t cB = (size_t)bh * Ss;

    for (int jt = 0; jt < 3; jt++) {
        const int j0 = jt * 128;
        __syncthreads();

        // K tile 128x64 -> tf32
        {
            const int r = tid >> 1, kh = (tid & 1) * 32;
            const float* p = Km + ((size_t)(b * Ss + j0 + r)) * Ee + h * Dd + kh;
#pragma unroll
            for (int i = 0; i < 8; i++) {
                float4 v = *(const float4*)(p + 4 * i);
                uint4 u; u.x = f2tf32(v.x); u.y = f2tf32(v.y);
                         u.z = f2tf32(v.z); u.w = f2tf32(v.w);
                *(uint4*)&KV[r * LDQ + kh + 4 * i] = u;
            }
        }
        if (tid < 128) msk[tid] = mask[b * Ss + j0 + tid];
        __syncthreads();

        // ---- S = Q K^T : M=64, N=128, K=64 ----
        float accS[2][4][4];
#pragma unroll
        for (int mf = 0; mf < 2; mf++)
#pragma unroll
            for (int nf = 0; nf < 4; nf++)
#pragma unroll
                for (int c = 0; c < 4; c++) accS[mf][nf][c] = 0.f;

#pragma unroll
        for (int kk = 0; kk < 8; kk++) {
            const int kb = kk * 8;
            uint32_t a[2][4];
#pragma unroll
            for (int mf = 0; mf < 2; mf++) {
                const int mr = wm + mf * 16 + qr;
                a[mf][0] = Qs[mr * LDQ + kb + qc];
                a[mf][1] = Qs[(mr + 8) * LDQ + kb + qc];
                a[mf][2] = Qs[mr * LDQ + kb + qc + 4];
                a[mf][3] = Qs[(mr + 8) * LDQ + kb + qc + 4];
            }
#pragma unroll
            for (int nf = 0; nf < 4; nf++) {
                const int nr = wn + nf * 8 + qr;
                const uint32_t b0 = KV[nr * LDQ + kb + qc];
                const uint32_t b1 = KV[nr * LDQ + kb + qc + 4];
                mma8(accS[0][nf], a[0][0], a[0][1], a[0][2], a[0][3], b0, b1);
                mma8(accS[1][nf], a[1][0], a[1][1], a[1][2], a[1][3], b0, b1);
            }
        }

        // ---- biases + scale + mask -> Ps ----
#pragma unroll
        for (int mf = 0; mf < 2; mf++) {
#pragma unroll
            for (int half = 0; half < 2; half++) {
                const int rl = wm + mf * 16 + qr + half * 8;
                const int ig = i0 + rl;
                const float* ckRow = Ck + (cB + ig) * RP + (j0 - ig + 383);
#pragma unroll
                for (int nf = 0; nf < 4; nf++) {
                    const int col = wn + nf * 8 + 2 * qc;
                    const int jg = j0 + col;
                    const int rr = jg - ig + 383;
                    float v0 = accS[mf][nf][half * 2 + 0]
                             + __ldg(ckRow + col)
                             + __ldg(Cq + (cB + jg) * RP + rr);
                    float v1 = accS[mf][nf][half * 2 + 1]
                             + __ldg(ckRow + col + 1)
                             + __ldg(Cq + (cB + jg + 1) * RP + rr + 1);
                    v0 *= SCALE_F; v1 *= SCALE_F;
                    if (msk[col] == 0)     v0 = -9.0e15f;
                    if (msk[col + 1] == 0) v1 = -9.0e15f;
                    *(float2*)&Ps[rl * LDP + col] = make_float2(v0, v1);
                }
            }
        }
        __syncthreads();

        // ---- V tile -> V^T tf32 (aliases KV) ----
        {
            const int d4 = (tid & 15) * 4, jb = tid >> 4;
            const float* vb = V + ((size_t)(b * Ss + j0)) * Ee + h * Dd + d4;
#pragma unroll
            for (int p2 = 0; p2 < 8; p2++) {
                const int jj = jb + p2 * 16;
                float4 v = *(const float4*)(vb + (size_t)jj * Ee);
                KV[(d4 + 0) * LDV + jj] = f2tf32(v.x);
                KV[(d4 + 1) * LDV + jj] = f2tf32(v.y);
                KV[(d4 + 2) * LDV + jj] = f2tf32(v.z);
                KV[(d4 + 3) * LDV + jj] = f2tf32(v.w);
            }
        }

        // ---- online softmax: 4 threads per row ----
        {
            const int row = tid >> 2, q = tid & 3;
            float* pr = Ps + row * LDP;
            const float mo = mrow[row];
            float mx = mo;
#pragma unroll 8
            for (int t = 0; t < 32; t++) mx = fmaxf(mx, pr[q + 4 * t]);
            mx = fmaxf(mx, __shfl_xor_sync(0xffffffffu, mx, 1));
            mx = fmaxf(mx, __shfl_xor_sync(0xffffffffu, mx, 2));
            float sum = 0.f;
#pragma unroll 8
            for (int t = 0; t < 32; t++) {
                const int c = q + 4 * t;
                const float p = __expf(pr[c] - mx);
                sum += p;
                ((uint32_t*)pr)[c] = f2tf32(p);
            }
            sum += __shfl_xor_sync(0xffffffffu, sum, 1);
            sum += __shfl_xor_sync(0xffffffffu, sum, 2);
            if (q == 0) {
                const float cf = __expf(mo - mx);
                crow[row] = cf;
                mrow[row] = mx;
                lrow[row] = lrow[row] * cf + sum;
            }
        }
        __syncthreads();

        // ---- O = O*cf + P @ V : M=64, N=64, K=128 ----
        {
            float cf0[2], cf1[2];
#pragma unroll
            for (int mf = 0; mf < 2; mf++) {
                cf0[mf] = crow[wm + mf * 16 + qr];
                cf1[mf] = crow[wm + mf * 16 + qr + 8];
            }
#pragma unroll
            for (int mf = 0; mf < 2; mf++)
#pragma unroll
                for (int nf = 0; nf < 2; nf++) {
                    accO[mf][nf][0] *= cf0[mf]; accO[mf][nf][1] *= cf0[mf];
                    accO[mf][nf][2] *= cf1[mf]; accO[mf][nf][3] *= cf1[mf];
                }
#pragma unroll
            for (int kk = 0; kk < 16; kk++) {
                const int kb = kk * 8;
                uint32_t a[2][4];
#pragma unroll
                for (int mf = 0; mf < 2; mf++) {
                    const int mr = wm + mf * 16 + qr;
                    a[mf][0] = PsU[mr * LDP + kb + qc];
                    a[mf][1] = PsU[(mr + 8) * LDP + kb + qc];
                    a[mf][2] = PsU[mr * LDP + kb + qc + 4];
                    a[mf][3] = PsU[(mr + 8) * LDP + kb + qc + 4];
                }
#pragma unroll
                for (int nf = 0; nf < 2; nf++) {
                    const int nr = wn2 + nf * 8 + qr;
                    const uint32_t b0 = KV[nr * LDV + kb + qc];
                    const uint32_t b1 = KV[nr * LDV + kb + qc + 4];
                    mma8(accO[0][nf], a[0][0], a[0][1], a[0][2], a[0][3], b0, b1);
                    mma8(accO[1][nf], a[1][0], a[1][1], a[1][2], a[1][3], b0, b1);
                }
            }
        }
    }

    // ---- finalize ----
#pragma unroll
    for (int mf = 0; mf < 2; mf++) {
#pragma unroll
        for (int half = 0; half < 2; half++) {
            const int rl = wm + mf * 16 + qr + half * 8;
            const float inv = 1.f / lrow[rl];
#pragma unroll
            for (int nf = 0; nf < 2; nf++) {
                const int col = wn2 + nf * 8 + 2 * qc;
                float2 o;
                o.x = accO[mf][nf][half * 2 + 0] * inv;
                o.y = accO[mf][nf][half * 2 + 1] * inv;
                *(float2*)&ctx[((size_t)(b * Ss + i0 + rl)) * Ee + h * Dd + col] = o;
            }
        }
    }
}

// =====================================================================
// Host launcher
// =====================================================================
extern "C" void kernel_launch(void* const* d_in, const int* in_sizes, int n_in,
                              void* d_out, int out_size)
{
    const float* x    = (const float*)d_in[0];
    const int*   mask = (const int*)  d_in[1];
    const float* Wq   = (const float*)d_in[2];
    const float* bq   = (const float*)d_in[3];
    const float* Wk   = (const float*)d_in[4];
    const float* bk   = (const float*)d_in[5];
    const float* Wv   = (const float*)d_in[6];
    const float* bv   = (const float*)d_in[7];
    const float* rel  = (const float*)d_in[8];
    const float* Wpk  = (const float*)d_in[9];
    const float* bpk  = (const float*)d_in[10];
    const float* Wpq  = (const float*)d_in[11];
    const float* bpq  = (const float*)d_in[12];
    const float* Wo   = (const float*)d_in[13];
    const float* bo   = (const float*)d_in[14];
    float* out = (float*)d_out;

    float *Q, *Km, *V, *ctx, *Pk, *Pq, *Ck, *Cq;
    cudaGetSymbolAddress((void**)&Q,   g_Q);
    cudaGetSymbolAddress((void**)&Km,  g_Km);
    cudaGetSymbolAddress((void**)&V,   g_V);
    cudaGetSymbolAddress((void**)&ctx, g_ctx);
    cudaGetSymbolAddress((void**)&Pk,  g_Pk);
    cudaGetSymbolAddress((void**)&Pq,  g_Pq);
    cudaGetSymbolAddress((void**)&Ck,  g_Ck);
    cudaGetSymbolAddress((void**)&Cq,  g_Cq);

    cudaFuncSetAttribute(attn_mma,
                         cudaFuncAttributeMaxDynamicSharedMemorySize, ATTN_SMEM);

    const float* relS = rel + 128 * 512;   // only rows 128..894 reachable (S < MAXL)

    // 1) Fused projections: 64-row tiles -> grid 960, 2 CTAs/SM co-residency
    ProjArgs pa;
    pa.s[0] = { x,    Wq,  bq,  Q,   MSn };
    pa.s[1] = { x,    Wk,  bk,  Km,  MSn };
    pa.s[2] = { x,    Wv,  bv,  V,   MSn };
    pa.s[3] = { relS, Wpk, bpk, Pk,  Rr  };
    pa.s[4] = { relS, Wpq, bpq, Pq,  Rr  };
    tf32_proj<<<dim3(4, 48, 5), 256>>>(pa);

    // 2) Windowed per-head bias GEMMs (R4 config)
    tf32_head<<<dim3(4, 3, 2 * BHn), 256>>>(Q, Km, Pk, Pq, Ck, Cq);

    // 3) Fused tensor-core attention (R4 version)
    attn_mma<<<dim3(6, BHn), 256, ATTN_SMEM>>>(Q, Km, V, Ck, Cq, mask, ctx);

    // 4) Output projection (64-row tiles)
    ProjArgs po;
    po.s[0] = { ctx, Wo, bo, out, MSn };
    po.s[1] = po.s[0]; po.s[2] = po.s[0]; po.s[3] = po.s[0]; po.s[4] = po.s[0];
    tf32_proj<<<dim3(4, 48, 1), 256>>>(po);
}